// round 1
// baseline (speedup 1.0000x reference)
#include <cuda_runtime.h>

// ---------------- problem constants ----------------
#define V_N   7
#define NB    256
#define KTOT  16384      // C*T = 256*64
#define OE    256
#define MTOT  1792       // NB * V_N
#define H_NSTR 114688    // C*T*V = stride of n in h
#define H_CSTR 448       // T*V   = stride of c in h

// ---------------- GEMM tiling ----------------
#define KSPLIT 8
#define KCHUNK 2048
#define KTILE  32
#define NKT    64        // KCHUNK / KTILE
#define MT     128       // M rows per CTA
// SMEM layouts (floats)
#define AS_NSTR 232                 // per-n stride in raw A tile (224 data + pad)
#define AS_SZ   (20 * AS_NSTR)      // up to 20 n's per M-block -> 4640
#define BS_STR  264                 // 256 + 8 pad (bank-conflict free frag reads)
#define BS_SZ   (32 * BS_STR)       // 8448
#define BUF_SZ  (AS_SZ + BS_SZ)     // 13088 floats per buffer
#define SMEM_BYTES (2 * BUF_SZ * 4) // 104704 bytes

// ---------------- device scratch ----------------
__device__ float g_Wr[KTOT * OE];            // tf32-rounded W (16.8 MB)
__device__ float g_part[KSPLIT * MTOT * OE]; // K-split partial Wh (14.7 MB)
__device__ float g_adjn[49];                 // normalized adjacency

__device__ __forceinline__ unsigned f2tf(float x) {
    unsigned r;
    asm("cvt.rna.tf32.f32 %0, %1;" : "=r"(r) : "f"(x));
    return r;
}

#define CP_ASYNC_16(smem_u32, gptr) \
    asm volatile("cp.async.cg.shared.global [%0], [%1], 16;\n" :: "r"(smem_u32), "l"(gptr) : "memory")

#define MMA_TF32(c, A, B) \
    asm volatile("mma.sync.aligned.m16n8k8.row.col.f32.tf32.tf32.f32 " \
                 "{%0,%1,%2,%3},{%4,%5,%6,%7},{%8,%9},{%0,%1,%2,%3};\n" \
                 : "+f"(c[0]), "+f"(c[1]), "+f"(c[2]), "+f"(c[3]) \
                 : "r"(A[0]), "r"(A[1]), "r"(A[2]), "r"(A[3]), "r"(B[0]), "r"(B[1]))

// ================= prep: round W to tf32, compute adj_norm =================
__global__ void prep_kernel(const float* __restrict__ W, const float* __restrict__ Bp) {
    int i = blockIdx.x * 256 + threadIdx.x;   // exactly KTOT*OE/4 float4's
    float4 v = ((const float4*)W)[i];
    v.x = __uint_as_float(f2tf(v.x));
    v.y = __uint_as_float(f2tf(v.y));
    v.z = __uint_as_float(f2tf(v.z));
    v.w = __uint_as_float(f2tf(v.w));
    ((float4*)g_Wr)[i] = v;

    if (blockIdx.x == 0 && threadIdx.x == 0) {
        float adj[49];
        float mn = 1e30f, mx = -1e30f;
        for (int k = 0; k < 49; k++) {
            float x = Bp[k] + 1e-6f + ((k / 7) == (k % 7) ? 1.0f : 0.0f);
            adj[k] = x;
            mn = fminf(mn, x);
            mx = fmaxf(mx, x);
        }
        float inv = 1.0f / (mx - mn);
        float dsum[7];
        for (int i2 = 0; i2 < 7; i2++) {
            float s = 0.0f;
            for (int j = 0; j < 7; j++) {
                adj[i2 * 7 + j] = (adj[i2 * 7 + j] - mn) * inv;
                s += adj[i2 * 7 + j];
            }
            dsum[i2] = s;
        }
        for (int i2 = 0; i2 < 7; i2++) {
            float di = 1.0f / sqrtf(dsum[i2]);
            for (int j = 0; j < 7; j++)
                g_adjn[i2 * 7 + j] = adj[i2 * 7 + j] * di / sqrtf(dsum[j]);
        }
    }
}

// ================= main GEMM: partial Wh = hf @ W (tf32 mma.sync) =================
__global__ void __launch_bounds__(512, 1) gemm_kernel(const float* __restrict__ h) {
    extern __shared__ float sm[];
    const int tid = threadIdx.x;
    const int ks  = blockIdx.x;          // K-split index
    const int mb  = blockIdx.y;          // M block
    const int m0  = mb * MT;
    const int n_first = m0 / 7;
    const int n_last  = (m0 + MT - 1) / 7;
    const int nCnt = n_last - n_first + 1;       // <= 20
    const int kc0 = ks * KCHUNK;

    // ---- staging index precompute ----
    int offB[4], dstB[4];
#pragma unroll
    for (int q = 0; q < 4; q++) {
        int f = tid + q * 512;           // float4 id in 32x256 B tile
        int kl = f >> 6, c4 = f & 63;
        offB[q] = kl * 256 + c4 * 4;
        dstB[q] = kl * BS_STR + c4 * 4;
    }
    int srcA[3], dstA[3];
    bool vA[3];
    const int nA = nCnt * 56;            // float4 count in A region
#pragma unroll
    for (int q = 0; q < 3; q++) {
        int f = tid + q * 512;
        vA[q] = (f < nA);
        int nr = f / 56, s4 = f - nr * 56;
        srcA[q] = (n_first + nr) * H_NSTR + s4 * 4;
        dstA[q] = nr * AS_NSTR + s4 * 4;
    }

    // ---- fragment geometry ----
    const int w = tid >> 5, lane = tid & 31;
    const int g = lane >> 2, t4 = lane & 3;
    const int wm = w >> 2, wn = w & 3;   // 4x4 warp grid, warp tile 32(M) x 64(O)
    int baseA[2][2];
#pragma unroll
    for (int mi = 0; mi < 2; mi++)
#pragma unroll
        for (int r = 0; r < 2; r++) {
            int gm = m0 + wm * 32 + mi * 16 + g + r * 8;
            int nn = gm / 7;
            baseA[mi][r] = (nn - n_first) * AS_NSTR + (gm - nn * 7);
        }

    float acc[2][8][4];
#pragma unroll
    for (int mi = 0; mi < 2; mi++)
#pragma unroll
        for (int ni = 0; ni < 8; ni++)
#pragma unroll
            for (int r = 0; r < 4; r++) acc[mi][ni][r] = 0.0f;

    auto issue = [&](int it, int buf) {
        const int kt = kc0 + it * KTILE;
        float* As = sm + buf * BUF_SZ;
        float* Bs = As + AS_SZ;
        unsigned aB = (unsigned)__cvta_generic_to_shared(Bs);
        const float* wsrc = g_Wr + (size_t)kt * 256;
#pragma unroll
        for (int q = 0; q < 4; q++) CP_ASYNC_16(aB + dstB[q] * 4, wsrc + offB[q]);
        const int hoff = (kt >> 6) * H_CSTR + (kt & 63) * 7;
        unsigned aA = (unsigned)__cvta_generic_to_shared(As);
#pragma unroll
        for (int q = 0; q < 3; q++)
            if (vA[q]) CP_ASYNC_16(aA + dstA[q] * 4, h + srcA[q] + hoff);
        asm volatile("cp.async.commit_group;\n" ::: "memory");
    };

    issue(0, 0);
    for (int it = 0; it < NKT; ++it) {
        if (it + 1 < NKT) {
            issue(it + 1, (it + 1) & 1);
            asm volatile("cp.async.wait_group 1;\n" ::: "memory");
        } else {
            asm volatile("cp.async.wait_group 0;\n" ::: "memory");
        }
        __syncthreads();
        const float* As = sm + (it & 1) * BUF_SZ;
        const float* Bs = As + AS_SZ;
#pragma unroll
        for (int kk = 0; kk < 4; kk++) {
            const int k = kk * 8 + t4;
            unsigned Af[2][4];
#pragma unroll
            for (int mi = 0; mi < 2; mi++) {
                Af[mi][0] = f2tf(As[baseA[mi][0] + k * 7]);
                Af[mi][1] = f2tf(As[baseA[mi][1] + k * 7]);
                Af[mi][2] = f2tf(As[baseA[mi][0] + (k + 4) * 7]);
                Af[mi][3] = f2tf(As[baseA[mi][1] + (k + 4) * 7]);
            }
            unsigned Bf[8][2];
            const int bb = k * BS_STR + wn * 64 + g;
#pragma unroll
            for (int ni = 0; ni < 8; ni++) {
                Bf[ni][0] = __float_as_uint(Bs[bb + ni * 8]);
                Bf[ni][1] = __float_as_uint(Bs[bb + ni * 8 + 4 * BS_STR]);
            }
#pragma unroll
            for (int mi = 0; mi < 2; mi++)
#pragma unroll
                for (int ni = 0; ni < 8; ni++) MMA_TF32(acc[mi][ni], Af[mi], Bf[ni]);
        }
        __syncthreads();
    }

    // ---- epilogue: write partial tile ----
    float* op = g_part + ((size_t)ks * MTOT + m0) * OE;
#pragma unroll
    for (int mi = 0; mi < 2; mi++)
#pragma unroll
        for (int ni = 0; ni < 8; ni++) {
            int r = wm * 32 + mi * 16 + g;
            int c = wn * 64 + ni * 8 + 2 * t4;
            float2 v01 = make_float2(acc[mi][ni][0], acc[mi][ni][1]);
            float2 v23 = make_float2(acc[mi][ni][2], acc[mi][ni][3]);
            *(float2*)&op[(size_t)r * OE + c] = v01;
            *(float2*)&op[(size_t)(r + 8) * OE + c] = v23;
        }
}

// ================= tail: reduce partials, attention, epilogue =================
__global__ void tail_kernel(const float* __restrict__ a, float* __restrict__ out) {
    __shared__ float red1[8][7], red2[8][7];
    __shared__ float s1s[7], s2s[7];
    __shared__ float adjn_s[49], att[49], att2[49];

    const int n = blockIdx.x;
    const int o = threadIdx.x;

    // sum K-split partials: Wh[n][v][o]
    float wh[7];
#pragma unroll
    for (int v = 0; v < 7; v++) {
        float s = 0.0f;
#pragma unroll
        for (int ksi = 0; ksi < KSPLIT; ksi++)
            s += g_part[((size_t)ksi * MTOT + n * 7 + v) * OE + o];
        wh[v] = s;
    }
    if (o < 49) adjn_s[o] = g_adjn[o];

    const float a1 = a[o];
    const float a2 = a[OE + o];
    const int wid = o >> 5, lane = o & 31;
#pragma unroll
    for (int v = 0; v < 7; v++) {
        float p1 = wh[v] * a1;
        float p2 = wh[v] * a2;
#pragma unroll
        for (int off = 16; off > 0; off >>= 1) {
            p1 += __shfl_down_sync(0xffffffffu, p1, off);
            p2 += __shfl_down_sync(0xffffffffu, p2, off);
        }
        if (lane == 0) { red1[wid][v] = p1; red2[wid][v] = p2; }
    }
    __syncthreads();
    if (o < 7) {
        float s = 0.0f;
        for (int w2 = 0; w2 < 8; w2++) s += red1[w2][o];
        s1s[o] = s;
    } else if (o >= 32 && o < 39) {
        float s = 0.0f;
        for (int w2 = 0; w2 < 8; w2++) s += red2[w2][o - 32];
        s2s[o - 32] = s;
    }
    __syncthreads();
    if (o < 7) {
        float e[7];
        float mx = -1e30f;
#pragma unroll
        for (int j = 0; j < 7; j++) {
            float x = s1s[o] + s2s[j];
            x = (x >= 0.0f) ? x : 0.2f * x;   // leaky_relu alpha=0.2
            e[j] = x;
            mx = fmaxf(mx, x);
        }
        float sum = 0.0f;
#pragma unroll
        for (int j = 0; j < 7; j++) { e[j] = expf(e[j] - mx); sum += e[j]; }
        float inv = 1.0f / sum;
#pragma unroll
        for (int j = 0; j < 7; j++) att[o * 7 + j] = e[j] * inv;
    }
    __syncthreads();
    if (o < 49) {
        int i = o / 7, kcol = o - i * 7;
        float s = 0.0f;
#pragma unroll
        for (int j = 0; j < 7; j++) s += adjn_s[i * 7 + j] * att[j * 7 + kcol];
        att2[o] = s;
    }
    __syncthreads();
#pragma unroll
    for (int v = 0; v < 7; v++) {
        float s = 0.0f;
#pragma unroll
        for (int j = 0; j < 7; j++) s += att2[v * 7 + j] * wh[j];
        out[((size_t)n * 7 + v) * OE + o] = (s > 0.0f) ? s : expm1f(s);  // elu
    }
}

// ================= launch =================
extern "C" void kernel_launch(void* const* d_in, const int* in_sizes, int n_in,
                              void* d_out, int out_size) {
    const float* h  = (const float*)d_in[0];   // (256,256,64,7)
    const float* W  = (const float*)d_in[1];   // (16384,256)
    const float* a  = (const float*)d_in[2];   // (512,1)
    const float* Bp = (const float*)d_in[3];   // (7,7)
    float* out = (float*)d_out;                // (256,7,256)

    prep_kernel<<<KTOT * OE / 4 / 256, 256>>>(W, Bp);

    cudaFuncSetAttribute(gemm_kernel, cudaFuncAttributeMaxDynamicSharedMemorySize, SMEM_BYTES);
    gemm_kernel<<<dim3(KSPLIT, MTOT / MT), 512, SMEM_BYTES>>>(h);

    tail_kernel<<<NB, OE>>>(a, out);
}